// round 1
// baseline (speedup 1.0000x reference)
#include <cuda_runtime.h>

// Izhikevich network: 5 recorded neurons, strictly sequential scan over T steps.
// Single block: 256 threads reduce input_mat -> z_plus; thread 0 runs the scan.
// Output layout: [ spikes[5][T] | volts[5][T] ]  (out_size = 10*T)

#define KDT 0.25f  // TAU * DT = 250 * 0.001

__device__ __forceinline__ void izh_step(float& v, float& u, float I,
                                         float a, float b, float c, float d,
                                         float& z) {
    float v1 = v + KDT * (0.04f * v * v + 5.0f * v + 140.0f - u + I);
    float u1 = u + (KDT * a) * (b * v - u);
    bool sp = (v1 >= 30.0f);
    z = sp ? 1.0f : 0.0f;
    v = sp ? c : v1;
    u = u1 + z * d;
}

__global__ void __launch_bounds__(256, 1)
izh_net_kernel(const float* __restrict__ in_mat, int n_mat,
               const float* __restrict__ w12,
               float* __restrict__ out, int T) {
    __shared__ float red[256];
    int tid = threadIdx.x;

    // ---- Phase 1: reduce input_mat -> sum (all 256 threads) ----
    float s = 0.0f;
    for (int i = tid; i < n_mat; i += 256) s += in_mat[i];
    red[tid] = s;
    __syncthreads();
    #pragma unroll
    for (int off = 128; off > 0; off >>= 1) {
        if (tid < off) red[tid] += red[tid + off];
        __syncthreads();
    }
    if (tid != 0) return;

    // ---- Phase 2: sequential scan on thread 0 ----
    float w[12];
    #pragma unroll
    for (int i = 0; i < 12; i++) w[i] = w12[i];

    const float z_plus = red[0] * w[0];

    // state
    float temp = 0.0f;
    float z2p = 0.0f, v2 = -60.0f, u2 = 4.5f;     // LLBN
    float v3 = -64.0f, u3 = -16.0f;               // EBN
    float v4 = -64.0f, u4 = -16.0f;               // IFN
    float z5p = 0.0f, v5 = -70.0f, u5 = -14.0f;   // TN
    float v6 = -64.0f, u6 = -16.0f;               // MN

    float* o_z = out;          // spikes [5][T]
    float* o_v = out + 5 * T;  // volts  [5][T]

    // loop-invariant pieces of input currents
    const float llbn_base = z_plus * w[1];   // inside w2*(z_plus*w1 - temp)
    const float ebn_base  = z_plus * w[4];

    int t0 = 0;
    if ((T & 3) == 0) {
        // fast path: unroll-by-4, vector stores (out is 256B-aligned, T%4==0)
        for (t0 = 0; t0 < T; t0 += 4) {
            float zb[5][4], vb[5][4];
            #pragma unroll
            for (int j = 0; j < 4; j++) {
                float z2, z3, z4, z5, z6;
                float I2 = w[2] * (llbn_base - temp) + w[3] * z2p;
                izh_step(v2, u2, I2, 0.1f, -0.075f, -55.0f, 6.0f, z2);
                float I3 = ebn_base + z2 * w[5];
                izh_step(v3, u3, I3, 0.02f, 0.25f, -55.0f, 0.05f, z3);
                izh_step(v4, u4, z3 * w[6], 0.02f, 0.25f, -65.0f, 6.0f, z4);
                temp = z4 * w[7];
                float I5 = w[9] * (z3 * w[8]) + w[10] * z5p;
                izh_step(v5, u5, I5, 0.02f, 0.2f, -65.0f, 6.0f, z5);
                izh_step(v6, u6, z5 * w[11], 0.02f, 0.25f, -65.0f, 6.0f, z6);
                z2p = z2; z5p = z5;
                zb[0][j] = z2; zb[1][j] = z3; zb[2][j] = z4; zb[3][j] = z5; zb[4][j] = z6;
                vb[0][j] = v2; vb[1][j] = v3; vb[2][j] = v4; vb[3][j] = v5; vb[4][j] = v6;
            }
            #pragma unroll
            for (int i = 0; i < 5; i++) {
                *reinterpret_cast<float4*>(o_z + i * T + t0) =
                    make_float4(zb[i][0], zb[i][1], zb[i][2], zb[i][3]);
                *reinterpret_cast<float4*>(o_v + i * T + t0) =
                    make_float4(vb[i][0], vb[i][1], vb[i][2], vb[i][3]);
            }
        }
    } else {
        // scalar fallback
        for (int t = 0; t < T; t++) {
            float z2, z3, z4, z5, z6;
            float I2 = w[2] * (llbn_base - temp) + w[3] * z2p;
            izh_step(v2, u2, I2, 0.1f, -0.075f, -55.0f, 6.0f, z2);
            float I3 = ebn_base + z2 * w[5];
            izh_step(v3, u3, I3, 0.02f, 0.25f, -55.0f, 0.05f, z3);
            izh_step(v4, u4, z3 * w[6], 0.02f, 0.25f, -65.0f, 6.0f, z4);
            temp = z4 * w[7];
            float I5 = w[9] * (z3 * w[8]) + w[10] * z5p;
            izh_step(v5, u5, I5, 0.02f, 0.2f, -65.0f, 6.0f, z5);
            izh_step(v6, u6, z5 * w[11], 0.02f, 0.25f, -65.0f, 6.0f, z6);
            z2p = z2; z5p = z5;
            o_z[0 * T + t] = z2; o_z[1 * T + t] = z3; o_z[2 * T + t] = z4;
            o_z[3 * T + t] = z5; o_z[4 * T + t] = z6;
            o_v[0 * T + t] = v2; o_v[1 * T + t] = v3; o_v[2 * T + t] = v4;
            o_v[3 * T + t] = v5; o_v[4 * T + t] = v6;
        }
    }
}

extern "C" void kernel_launch(void* const* d_in, const int* in_sizes, int n_in,
                              void* d_out, int out_size) {
    const float* in_mat = (const float*)d_in[0];
    const float* w12    = (const float*)d_in[1];
    int n_mat = in_sizes[0];
    int T = out_size / 10;  // out = spikes[5][T] + volts[5][T]
    izh_net_kernel<<<1, 256>>>(in_mat, n_mat, w12, (float*)d_out, T);
}

// round 2
// speedup vs baseline: 1.3086x; 1.3086x over previous
#include <cuda_runtime.h>

// Izhikevich 6-neuron network, T sequential steps.
// Warp0: LLBN->EBN->IFN recurrence (critical).  Warp1: TN->MN (feed-forward from z3).
// Warp2: 32-lane store warp. Shared ring buffer + acquire/release flags.
// Output: [spikes[5][T] | volts[5][T]]

#define BATCH 32
#define RING_STEPS 256
#define RING_MASK 255
#define RING_BATCHES 8

__device__ __forceinline__ float fset_ge30(float a) {
    float r;
    asm("set.ge.f32.f32 %0, %1, %2;" : "=f"(r) : "f"(a), "f"(30.0f));
    return r;
}
__device__ __forceinline__ void st_rel(int* p, int v) {
    asm volatile("st.release.cta.u32 [%0], %1;" :: "l"(p), "r"(v) : "memory");
}
__device__ __forceinline__ int ld_acq(int* p) {
    int v;
    asm volatile("ld.acquire.cta.u32 %0, [%1];" : "=r"(v) : "l"(p) : "memory");
    return v;
}

__global__ void __launch_bounds__(128, 1)
izh_net3(const float* __restrict__ in_mat, int n_mat,
         const float* __restrict__ w12, float* __restrict__ out, int T) {
    __shared__ __align__(16) float ring0[RING_STEPS * 8];  // z2,z3,z4,_,v2,v3,v4,_
    __shared__ __align__(16) float ring1[RING_STEPS * 4];  // z5,v5,z6,v6
    __shared__ float red[4];
    __shared__ int fl[3];  // p0 (warp0 batches done), p1 (warp1), cons (warp2)

    const int tid = threadIdx.x;
    if (tid == 0) { fl[0] = 0; fl[1] = 0; fl[2] = 0; }

    // ---- reduction: sum(input_mat), all 128 threads ----
    float s = 0.0f;
    for (int i = tid; i < n_mat; i += 128) s += in_mat[i];
    #pragma unroll
    for (int o = 16; o; o >>= 1) s += __shfl_xor_sync(0xffffffffu, s, o);
    if ((tid & 31) == 0) red[tid >> 5] = s;
    __syncthreads();

    const int nbat = (T + BATCH - 1) / BATCH;

    // ================= Warp 0, lane 0: LLBN -> EBN -> IFN =================
    if (tid == 0) {
        const float total = red[0] + red[1] + red[2] + red[3];
        const float w0 = w12[0], w1 = w12[1], w2 = w12[2], w3 = w12[3],
                    w4 = w12[4], w5 = w12[5], w6 = w12[6], w7 = w12[7];
        const float z_plus = total * w0;
        // folded coefficients (KDT = 0.25 distributed)
        const float C2 = 35.0f + 0.25f * w2 * (z_plus * w1);
        const float A2 = -0.25f * w2 * w7;  // * z4(t-1)   (temp feedback)
        const float B2 = 0.25f * w3;        // * z2(t-1)
        const float C3 = 35.0f + 0.25f * (z_plus * w4);
        const float A3 = 0.25f * w5;        // * z2(t)
        const float A4 = 0.25f * w6;        // * z3(t)

        float v2 = -60.0f, u2 = 4.5f;
        float v3 = -64.0f, u3 = -16.0f;
        float v4 = -64.0f, u4 = -16.0f;
        float z2p = 0.0f, z4p = 0.0f;

        int si = 0;
        for (int b = 0; b < nbat; ++b) {
            while (b - ld_acq(&fl[2]) >= RING_BATCHES) { }
            const int n = min(BATCH, T - b * BATCH);
            for (int i = 0; i < n; ++i, ++si) {
                // LLBN (a=0.1,b=-0.075,c=-55,d=6): u coefs 0.975 / -0.001875
                float vv2 = v2 * v2;
                float b2  = fmaf(vv2, 0.01f, fmaf(v2, 2.25f, fmaf(u2, -0.25f, C2)));
                float v12 = fmaf(z4p, A2, fmaf(z2p, B2, b2));
                float z2  = fset_ge30(v12);
                float nu2 = fmaf(u2, 0.975f, v2 * -0.001875f);
                v2 = fmaf(z2, -55.0f - v12, v12);
                u2 = fmaf(z2, 6.0f, nu2);
                // EBN (a=0.02,b=0.25,c=-55,d=0.05): 0.995 / 0.00125
                float vv3 = v3 * v3;
                float b3  = fmaf(vv3, 0.01f, fmaf(v3, 2.25f, fmaf(u3, -0.25f, C3)));
                float v13 = fmaf(z2, A3, b3);
                float z3  = fset_ge30(v13);
                float nu3 = fmaf(u3, 0.995f, v3 * 0.00125f);
                v3 = fmaf(z3, -55.0f - v13, v13);
                u3 = fmaf(z3, 0.05f, nu3);
                // IFN (a=0.02,b=0.25,c=-65,d=6): 0.995 / 0.00125
                float vv4 = v4 * v4;
                float b4  = fmaf(vv4, 0.01f, fmaf(v4, 2.25f, fmaf(u4, -0.25f, 35.0f)));
                float v14 = fmaf(z3, A4, b4);
                float z4  = fset_ge30(v14);
                float nu4 = fmaf(u4, 0.995f, v4 * 0.00125f);
                v4 = fmaf(z4, -65.0f - v14, v14);
                u4 = fmaf(z4, 6.0f, nu4);

                z2p = z2; z4p = z4;
                float4* r = (float4*)&ring0[(si & RING_MASK) * 8];
                r[0] = make_float4(z2, z3, z4, 0.0f);
                r[1] = make_float4(v2, v3, v4, 0.0f);
            }
            st_rel(&fl[0], b + 1);
        }
        return;
    }

    // ================= Warp 1, lane 0: TN -> MN =================
    if (tid == 32) {
        const float w8 = w12[8], w9 = w12[9], w10 = w12[10], w11 = w12[11];
        const float A5 = 0.25f * w9 * w8;  // * z3(t)
        const float B5 = 0.25f * w10;      // * z5(t-1)
        const float A6 = 0.25f * w11;      // * z5(t)
        float v5 = -70.0f, u5 = -14.0f;
        float v6 = -64.0f, u6 = -16.0f;
        float z5p = 0.0f;

        int si = 0;
        for (int b = 0; b < nbat; ++b) {
            while (ld_acq(&fl[0]) <= b) { }
            const int n = min(BATCH, T - b * BATCH);
            for (int i = 0; i < n; ++i, ++si) {
                float z3 = ring0[(si & RING_MASK) * 8 + 1];
                // TN (a=0.02,b=0.2,c=-65,d=6): 0.995 / 0.001
                float vv5 = v5 * v5;
                float b5  = fmaf(vv5, 0.01f, fmaf(v5, 2.25f, fmaf(u5, -0.25f, 35.0f)));
                float v15 = fmaf(z5p, B5, fmaf(z3, A5, b5));
                float z5  = fset_ge30(v15);
                float nu5 = fmaf(u5, 0.995f, v5 * 0.001f);
                v5 = fmaf(z5, -65.0f - v15, v15);
                u5 = fmaf(z5, 6.0f, nu5);
                // MN (a=0.02,b=0.25,c=-65,d=6): 0.995 / 0.00125
                float vv6 = v6 * v6;
                float b6  = fmaf(vv6, 0.01f, fmaf(v6, 2.25f, fmaf(u6, -0.25f, 35.0f)));
                float v16 = fmaf(z5, A6, b6);
                float z6  = fset_ge30(v16);
                float nu6 = fmaf(u6, 0.995f, v6 * 0.00125f);
                v6 = fmaf(z6, -65.0f - v16, v16);
                u6 = fmaf(z6, 6.0f, nu6);

                z5p = z5;
                ((float4*)&ring1[(si & RING_MASK) * 4])[0] = make_float4(z5, v5, z6, v6);
            }
            st_rel(&fl[1], b + 1);
        }
        return;
    }

    // ================= Warp 2: wide store warp =================
    if (tid >= 64 && tid < 96) {
        const int lane = tid - 64;
        // row -> (buffer, column):  z2 z3 z4 z5 z6 v2 v3 v4 v5 v6
        // buf:                       0  0  0  1  1  0  0  0  1  1   (mask 0x318)
        // col:                       0  1  2  0  2  4  5  6  1  3
        for (int b = 0; b < nbat; ++b) {
            while (ld_acq(&fl[1]) <= b) { }
            const int base = b * BATCH;
            const int n = min(BATCH, T - base);
            if ((T & 3) == 0) {
                const int quads = n >> 2;           // n is 32 or a multiple of 4
                const int units = 10 * quads;
                for (int u = lane; u < units; u += 32) {
                    const int row = u / quads;
                    const int q   = u - row * quads;
                    const int st  = base + q * 4;
                    const int buf = (0x318 >> row) & 1;
                    const int col = (row < 8) ? ((0x65420210u >> (4 * row)) & 15)
                                              : ((0x31u >> (4 * (row - 8))) & 15);
                    float x0, x1, x2, x3;
                    if (buf == 0) {
                        x0 = ring0[((st + 0) & RING_MASK) * 8 + col];
                        x1 = ring0[((st + 1) & RING_MASK) * 8 + col];
                        x2 = ring0[((st + 2) & RING_MASK) * 8 + col];
                        x3 = ring0[((st + 3) & RING_MASK) * 8 + col];
                    } else {
                        x0 = ring1[((st + 0) & RING_MASK) * 4 + col];
                        x1 = ring1[((st + 1) & RING_MASK) * 4 + col];
                        x2 = ring1[((st + 2) & RING_MASK) * 4 + col];
                        x3 = ring1[((st + 3) & RING_MASK) * 4 + col];
                    }
                    *(float4*)&out[row * T + st] = make_float4(x0, x1, x2, x3);
                }
            } else {
                // generic scalar fallback (T not multiple of 4)
                const int units = 10 * n;
                for (int u = lane; u < units; u += 32) {
                    const int row = u / n;
                    const int i   = u - row * n;
                    const int st  = base + i;
                    const int buf = (0x318 >> row) & 1;
                    const int col = (row < 8) ? ((0x65420210u >> (4 * row)) & 15)
                                              : ((0x31u >> (4 * (row - 8))) & 15);
                    float x = buf ? ring1[(st & RING_MASK) * 4 + col]
                                  : ring0[(st & RING_MASK) * 8 + col];
                    out[row * T + st] = x;
                }
            }
            __syncwarp();
            if (lane == 0) st_rel(&fl[2], b + 1);
        }
        return;
    }
}

extern "C" void kernel_launch(void* const* d_in, const int* in_sizes, int n_in,
                              void* d_out, int out_size) {
    const float* in_mat = (const float*)d_in[0];
    const float* w12    = (const float*)d_in[1];
    int n_mat = in_sizes[0];
    int T = out_size / 10;
    izh_net3<<<1, 128>>>(in_mat, n_mat, w12, (float*)d_out, T);
}